// round 2
// baseline (speedup 1.0000x reference)
#include <cuda_runtime.h>
#include <math.h>

#define EPSF 1e-8f
#define NMAX 50000
#define D1 128
#define D2 256

// Scratch (device globals — no allocation allowed). float4 for 16B alignment.
__device__ float4 g_agg1_[(size_t)NMAX * D1 / 4];
__device__ float4 g_h_[(size_t)NMAX * D2 / 4];
__device__ float4 g_agg2_[(size_t)NMAX * D2 / 4];
__device__ float  g_xnorm[NMAX];
__device__ float  g_hnorm[NMAX];
__device__ int    g_is64;

// ---------------------------------------------------------------------------
// edge_index dtype detection (jax may serialize int64 as int32)
// ---------------------------------------------------------------------------
__global__ void k_init_flag() { g_is64 = 1; }

__global__ void k_detect64(const void* __restrict__ eidx, int E, int N) {
    int i = blockIdx.x * blockDim.x + threadIdx.x;
    if (i < E) {
        long long v = ((const long long*)eidx)[i];
        if (v < 0 || v >= (long long)N) g_is64 = 0;
    }
}

// ---------------------------------------------------------------------------
// Per-node norms + self-loop init: agg[i] = (sim_self > 0.5) ? feat[i] : 0
// ---------------------------------------------------------------------------
template<int D>
__global__ void k_norms_init(const float* __restrict__ feat,
                             float* __restrict__ norms,
                             float* __restrict__ agg, int N)
{
    int node = (blockIdx.x * blockDim.x + threadIdx.x) >> 5;
    int lane = threadIdx.x & 31;
    if (node >= N) return;
    const float4* f = (const float4*)(feat + (size_t)node * D);
    float4* a = (float4*)(agg + (size_t)node * D);
    float4 v[D / 128];
    float n2 = 0.f;
#pragma unroll
    for (int i = 0; i < D / 128; i++) {
        v[i] = f[lane + 32 * i];
        n2 += v[i].x * v[i].x + v[i].y * v[i].y + v[i].z * v[i].z + v[i].w * v[i].w;
    }
#pragma unroll
    for (int o = 16; o; o >>= 1) n2 += __shfl_xor_sync(0xffffffffu, n2, o);
    float nrm = sqrtf(n2);
    if (lane == 0) norms[node] = nrm;
    float denom = fmaxf(nrm * nrm, EPSF);
    bool pass = n2 > 0.5f * denom;
    float4 z = make_float4(0.f, 0.f, 0.f, 0.f);
#pragma unroll
    for (int i = 0; i < D / 128; i++) a[lane + 32 * i] = pass ? v[i] : z;
}

// ---------------------------------------------------------------------------
// Edge pass: EPW edges per warp. All loads front-batched for MLP, then
// reductions, then guarded scatter-add.
// ---------------------------------------------------------------------------
template<int D, int EPW>
__global__ void k_edge_pass(const float* __restrict__ feat,
                            const float* __restrict__ norms,
                            const void* __restrict__ eidx,
                            float* __restrict__ agg, int E)
{
    constexpr int V = D / 128;  // float4 per lane per vector
    long long wid = (long long)((blockIdx.x * (unsigned)blockDim.x + threadIdx.x) >> 5);
    int lane = threadIdx.x & 31;
    long long base = wid * EPW;
    if (base >= E) return;
    const bool is64 = (g_is64 != 0);

    int s[EPW], d[EPW];
#pragma unroll
    for (int k = 0; k < EPW; k++) {
        long long e = base + k;
        if (e >= E) e = E - 1;  // duplicate tail edge; scatter guarded below
        if (is64) {
            const long long* p = (const long long*)eidx;
            s[k] = (int)p[e];
            d[k] = (int)p[e + E];
        } else {
            const int* p = (const int*)eidx;
            s[k] = p[e];
            d[k] = p[e + E];
        }
    }

    // Front-batch all feature loads (2*EPW*V independent LDG.128 per lane)
    float4 vs[EPW][V], vd[EPW][V];
#pragma unroll
    for (int k = 0; k < EPW; k++) {
        const float4* fs = (const float4*)(feat + (size_t)s[k] * D);
        const float4* fd = (const float4*)(feat + (size_t)d[k] * D);
#pragma unroll
        for (int i = 0; i < V; i++) {
            vs[k][i] = fs[lane + 32 * i];
            vd[k][i] = fd[lane + 32 * i];
        }
    }

    float dot[EPW];
#pragma unroll
    for (int k = 0; k < EPW; k++) {
        float t = 0.f;
#pragma unroll
        for (int i = 0; i < V; i++)
            t += vs[k][i].x * vd[k][i].x + vs[k][i].y * vd[k][i].y +
                 vs[k][i].z * vd[k][i].z + vs[k][i].w * vd[k][i].w;
#pragma unroll
        for (int o = 16; o; o >>= 1) t += __shfl_xor_sync(0xffffffffu, t, o);
        dot[k] = t;
    }

#pragma unroll
    for (int k = 0; k < EPW; k++) {
        if (base + k >= E) break;
        float thr = 0.5f * fmaxf(norms[s[k]] * norms[d[k]], EPSF);
        if (dot[k] > thr) {
            float* out = agg + (size_t)d[k] * D + lane * 4;
#pragma unroll
            for (int i = 0; i < V; i++) {
                asm volatile("red.global.add.v4.f32 [%0], {%1,%2,%3,%4};" ::
                             "l"(out + i * 128),
                             "f"(vs[k][i].x), "f"(vs[k][i].y),
                             "f"(vs[k][i].z), "f"(vs[k][i].w)
                             : "memory");
            }
        }
    }
}

// ---------------------------------------------------------------------------
// SGEMM: C[M,N] = A[M,K] @ W[N,K]^T + bias. RELU or fused log_softmax
// (LSM requires BN == N == 16*TN so each half-warp owns full rows).
// ---------------------------------------------------------------------------
template<int BM, int BN, int BK, int TM, int TN, int RELU, int LSM>
__global__ __launch_bounds__((BM / TM) * (BN / TN))
void k_sgemm(const float* __restrict__ A, const float* __restrict__ W,
             const float* __restrict__ bias, float* __restrict__ C,
             int M, int N, int K)
{
    constexpr int THREADS = (BM / TM) * (BN / TN);
    __shared__ float As[BK][BM];
    __shared__ float Ws[BK][BN];
    int tid = threadIdx.x;
    int tx = tid % (BN / TN);
    int ty = tid / (BN / TN);
    int m0 = blockIdx.y * BM;
    int n0 = blockIdx.x * BN;

    float acc[TM][TN] = {};
    constexpr int A_LD = BM * BK / 4;
    constexpr int W_LD = BN * BK / 4;

    for (int k0 = 0; k0 < K; k0 += BK) {
#pragma unroll
        for (int i = tid; i < A_LD; i += THREADS) {
            int m = i / (BK / 4);
            int kq = i % (BK / 4);
            int gm = m0 + m;
            if (gm >= M) gm = M - 1;
            float4 v = *(const float4*)(A + (size_t)gm * K + k0 + kq * 4);
            As[kq * 4 + 0][m] = v.x;
            As[kq * 4 + 1][m] = v.y;
            As[kq * 4 + 2][m] = v.z;
            As[kq * 4 + 3][m] = v.w;
        }
#pragma unroll
        for (int i = tid; i < W_LD; i += THREADS) {
            int n = i / (BK / 4);
            int kq = i % (BK / 4);
            float4 v = *(const float4*)(W + (size_t)(n0 + n) * K + k0 + kq * 4);
            Ws[kq * 4 + 0][n] = v.x;
            Ws[kq * 4 + 1][n] = v.y;
            Ws[kq * 4 + 2][n] = v.z;
            Ws[kq * 4 + 3][n] = v.w;
        }
        __syncthreads();
#pragma unroll
        for (int k = 0; k < BK; k++) {
            float rm[TM], rn[TN];
#pragma unroll
            for (int i = 0; i < TM; i++) rm[i] = As[k][ty * TM + i];
#pragma unroll
            for (int j = 0; j < TN; j++) rn[j] = Ws[k][tx * TN + j];
#pragma unroll
            for (int i = 0; i < TM; i++)
#pragma unroll
                for (int j = 0; j < TN; j++)
                    acc[i][j] += rm[i] * rn[j];
        }
        __syncthreads();
    }

#pragma unroll
    for (int i = 0; i < TM; i++) {
        int gm = m0 + ty * TM + i;
        float v[TN];
#pragma unroll
        for (int j = 0; j < TN; j++) {
            v[j] = acc[i][j] + bias[n0 + tx * TN + j];
            if (RELU) v[j] = fmaxf(v[j], 0.f);
        }
        if (LSM) {
            // 16 threads (tx 0..15) of this half-warp own the full row
            float mx = v[0];
#pragma unroll
            for (int j = 1; j < TN; j++) mx = fmaxf(mx, v[j]);
#pragma unroll
            for (int o = 1; o < 16; o <<= 1)
                mx = fmaxf(mx, __shfl_xor_sync(0xffffffffu, mx, o));
            float sm = 0.f;
#pragma unroll
            for (int j = 0; j < TN; j++) sm += expf(v[j] - mx);
#pragma unroll
            for (int o = 1; o < 16; o <<= 1)
                sm += __shfl_xor_sync(0xffffffffu, sm, o);
            float l = mx + logf(sm);
#pragma unroll
            for (int j = 0; j < TN; j++) v[j] -= l;
        }
        if (gm < M) {
            if (TN == 4) {
                *(float4*)(C + (size_t)gm * N + n0 + tx * TN) =
                    make_float4(v[0], v[1], v[2], v[3]);
            } else {
#pragma unroll
                for (int j = 0; j < TN; j++)
                    C[(size_t)gm * N + n0 + tx * TN + j] = v[j];
            }
        }
    }
}

// ---------------------------------------------------------------------------
extern "C" void kernel_launch(void* const* d_in, const int* in_sizes, int n_in,
                              void* d_out, int out_size)
{
    const float* x   = (const float*)d_in[0];
    const void*  eix = d_in[1];
    const float* W1  = (const float*)d_in[2];
    const float* b1  = (const float*)d_in[3];
    const float* W2  = (const float*)d_in[4];
    const float* b2  = (const float*)d_in[5];
    float* out = (float*)d_out;

    int N = in_sizes[0] / D1;      // 50000
    int E = in_sizes[1] / 2;       // 800000
    (void)n_in; (void)out_size;

    float *agg1, *h, *agg2, *xn, *hn;
    cudaGetSymbolAddress((void**)&agg1, g_agg1_);
    cudaGetSymbolAddress((void**)&h,    g_h_);
    cudaGetSymbolAddress((void**)&agg2, g_agg2_);
    cudaGetSymbolAddress((void**)&xn,   g_xnorm);
    cudaGetSymbolAddress((void**)&hn,   g_hnorm);

    // dtype detection for edge_index
    k_init_flag<<<1, 1>>>();
    k_detect64<<<(E + 255) / 256, 256>>>(eix, E, N);

    int nodeBlocks = (N * 32 + 255) / 256;

    // ---- Layer 1 (D=128, EPW=4) ----
    k_norms_init<D1><<<nodeBlocks, 256>>>(x, xn, agg1, N);
    {
        long long warps = ((long long)E + 3) / 4;
        int blocks = (int)((warps * 32 + 255) / 256);
        k_edge_pass<D1, 4><<<blocks, 256>>>(x, xn, eix, agg1, E);
    }
    {
        dim3 grid(256 / 128, (N + 127) / 128);
        k_sgemm<128, 128, 16, 8, 8, 1, 0><<<grid, 256>>>(agg1, W1, b1, h, N, 256, 128);
    }

    // ---- Layer 2 (D=256, EPW=2) ----
    k_norms_init<D2><<<nodeBlocks, 256>>>(h, hn, agg2, N);
    {
        long long warps = ((long long)E + 1) / 2;
        int blocks = (int)((warps * 32 + 255) / 256);
        k_edge_pass<D2, 2><<<blocks, 256>>>(h, hn, eix, agg2, E);
    }
    {
        dim3 grid(1, (N + 127) / 128);
        k_sgemm<128, 64, 16, 8, 4, 0, 1><<<grid, 256>>>(agg2, W2, b2, out, N, 64, 256);
    }
}

// round 3
// speedup vs baseline: 1.5628x; 1.5628x over previous
#include <cuda_runtime.h>
#include <math.h>

#define EPSF 1e-8f
#define NMAX 50000
#define D1 128
#define D2 256

// Scratch (device globals — no allocation allowed). float4 for 16B alignment.
__device__ float4 g_agg1_[(size_t)NMAX * D1 / 4];
__device__ float4 g_h_[(size_t)NMAX * D2 / 4];
__device__ float4 g_agg2_[(size_t)NMAX * D2 / 4];
__device__ float  g_xnorm[NMAX];
__device__ float  g_hnorm[NMAX];
__device__ int    g_is64;

// ---------------------------------------------------------------------------
// edge_index dtype detection (jax may serialize int64 as int32)
// ---------------------------------------------------------------------------
__global__ void k_init_flag() { g_is64 = 1; }

__global__ void k_detect64(const void* __restrict__ eidx, int E, int N) {
    int i = blockIdx.x * blockDim.x + threadIdx.x;
    if (i < E) {
        long long v = ((const long long*)eidx)[i];
        if (v < 0 || v >= (long long)N) g_is64 = 0;
    }
}

// ---------------------------------------------------------------------------
// Per-node norms + self-loop init: agg[i] = (sim_self > 0.5) ? feat[i] : 0
// ---------------------------------------------------------------------------
template<int D>
__global__ void k_norms_init(const float* __restrict__ feat,
                             float* __restrict__ norms,
                             float* __restrict__ agg, int N)
{
    int node = (blockIdx.x * blockDim.x + threadIdx.x) >> 5;
    int lane = threadIdx.x & 31;
    if (node >= N) return;
    const float4* f = (const float4*)(feat + (size_t)node * D);
    float4* a = (float4*)(agg + (size_t)node * D);
    float4 v[D / 128];
    float n2 = 0.f;
#pragma unroll
    for (int i = 0; i < D / 128; i++) {
        v[i] = f[lane + 32 * i];
        n2 += v[i].x * v[i].x + v[i].y * v[i].y + v[i].z * v[i].z + v[i].w * v[i].w;
    }
#pragma unroll
    for (int o = 16; o; o >>= 1) n2 += __shfl_xor_sync(0xffffffffu, n2, o);
    float nrm = sqrtf(n2);
    if (lane == 0) norms[node] = nrm;
    float denom = fmaxf(nrm * nrm, EPSF);
    bool pass = n2 > 0.5f * denom;
    float4 z = make_float4(0.f, 0.f, 0.f, 0.f);
#pragma unroll
    for (int i = 0; i < D / 128; i++) a[lane + 32 * i] = pass ? v[i] : z;
}

// ---------------------------------------------------------------------------
// Edge pass, D=128, 2 edges per warp. norms prefetched; two interleaved
// shfl reduction chains hide each other's latency.
// ---------------------------------------------------------------------------
__global__ void k_edge_pass128(const float* __restrict__ feat,
                               const float* __restrict__ norms,
                               const void* __restrict__ eidx,
                               float* __restrict__ agg, int E)
{
    long long wid = (long long)((blockIdx.x * (unsigned)blockDim.x + threadIdx.x) >> 5);
    int lane = threadIdx.x & 31;
    long long base = wid * 2;
    if (base >= E) return;
    const bool is64 = (g_is64 != 0);

    int s[2], d[2];
#pragma unroll
    for (int k = 0; k < 2; k++) {
        long long e = base + k;
        if (e >= E) e = E - 1;  // duplicate tail; scatter guarded below
        if (is64) {
            const long long* p = (const long long*)eidx;
            s[k] = (int)p[e];
            d[k] = (int)p[e + E];
        } else {
            const int* p = (const int*)eidx;
            s[k] = p[e];
            d[k] = p[e + E];
        }
    }

    // Prefetch norms (broadcast loads) before the big vector loads
    float ns0 = norms[s[0]], nd0 = norms[d[0]];
    float ns1 = norms[s[1]], nd1 = norms[d[1]];

    float4 vs[2], vd[2];
#pragma unroll
    for (int k = 0; k < 2; k++) {
        vs[k] = ((const float4*)(feat + (size_t)s[k] * D1))[lane];
        vd[k] = ((const float4*)(feat + (size_t)d[k] * D1))[lane];
    }

    float t[2];
#pragma unroll
    for (int k = 0; k < 2; k++)
        t[k] = vs[k].x * vd[k].x + vs[k].y * vd[k].y +
               vs[k].z * vd[k].z + vs[k].w * vd[k].w;
    // interleaved butterflies
#pragma unroll
    for (int o = 16; o; o >>= 1) {
        t[0] += __shfl_xor_sync(0xffffffffu, t[0], o);
        t[1] += __shfl_xor_sync(0xffffffffu, t[1], o);
    }

    float thr0 = 0.5f * fmaxf(ns0 * nd0, EPSF);
    float thr1 = 0.5f * fmaxf(ns1 * nd1, EPSF);

    if (t[0] > thr0) {
        asm volatile("red.global.add.v4.f32 [%0], {%1,%2,%3,%4};" ::
                     "l"(agg + (size_t)d[0] * D1 + lane * 4),
                     "f"(vs[0].x), "f"(vs[0].y), "f"(vs[0].z), "f"(vs[0].w)
                     : "memory");
    }
    if (base + 1 < E && t[1] > thr1) {
        asm volatile("red.global.add.v4.f32 [%0], {%1,%2,%3,%4};" ::
                     "l"(agg + (size_t)d[1] * D1 + lane * 4),
                     "f"(vs[1].x), "f"(vs[1].y), "f"(vs[1].z), "f"(vs[1].w)
                     : "memory");
    }
}

// ---------------------------------------------------------------------------
// Edge pass, D=256, 1 edge per warp (register budget). norms prefetched.
// ---------------------------------------------------------------------------
__global__ void k_edge_pass256(const float* __restrict__ feat,
                               const float* __restrict__ norms,
                               const void* __restrict__ eidx,
                               float* __restrict__ agg, int E)
{
    int e = (int)((blockIdx.x * (unsigned)blockDim.x + threadIdx.x) >> 5);
    if (e >= E) return;
    int lane = threadIdx.x & 31;
    int s, d;
    if (g_is64) {
        const long long* p = (const long long*)eidx;
        s = (int)p[e];
        d = (int)p[e + E];
    } else {
        const int* p = (const int*)eidx;
        s = p[e];
        d = p[e + E];
    }
    float ns = norms[s], nd = norms[d];

    const float4* fs = (const float4*)(feat + (size_t)s * D2);
    const float4* fd = (const float4*)(feat + (size_t)d * D2);
    float4 vs[2], vdv[2];
#pragma unroll
    for (int i = 0; i < 2; i++) {
        vs[i] = fs[lane + 32 * i];
        vdv[i] = fd[lane + 32 * i];
    }
    // two independent partial chains, combined at the end
    float t0 = vs[0].x * vdv[0].x + vs[0].y * vdv[0].y +
               vs[0].z * vdv[0].z + vs[0].w * vdv[0].w;
    float t1 = vs[1].x * vdv[1].x + vs[1].y * vdv[1].y +
               vs[1].z * vdv[1].z + vs[1].w * vdv[1].w;
    float t = t0 + t1;
#pragma unroll
    for (int o = 16; o; o >>= 1) t += __shfl_xor_sync(0xffffffffu, t, o);

    float thr = 0.5f * fmaxf(ns * nd, EPSF);
    if (t > thr) {
        float* out = agg + (size_t)d * D2 + lane * 4;
#pragma unroll
        for (int i = 0; i < 2; i++) {
            asm volatile("red.global.add.v4.f32 [%0], {%1,%2,%3,%4};" ::
                         "l"(out + i * 128),
                         "f"(vs[i].x), "f"(vs[i].y), "f"(vs[i].z), "f"(vs[i].w)
                         : "memory");
        }
    }
}

// ---------------------------------------------------------------------------
// SGEMM: C[M,N] = A[M,K] @ W[N,K]^T + bias. RELU or fused log_softmax
// (LSM requires BN == N == 16*TN so each half-warp owns full rows).
// ---------------------------------------------------------------------------
template<int BM, int BN, int BK, int TM, int TN, int RELU, int LSM>
__global__ __launch_bounds__((BM / TM) * (BN / TN))
void k_sgemm(const float* __restrict__ A, const float* __restrict__ W,
             const float* __restrict__ bias, float* __restrict__ C,
             int M, int N, int K)
{
    constexpr int THREADS = (BM / TM) * (BN / TN);
    __shared__ float As[BK][BM];
    __shared__ float Ws[BK][BN];
    int tid = threadIdx.x;
    int tx = tid % (BN / TN);
    int ty = tid / (BN / TN);
    int m0 = blockIdx.y * BM;
    int n0 = blockIdx.x * BN;

    float acc[TM][TN] = {};
    constexpr int A_LD = BM * BK / 4;
    constexpr int W_LD = BN * BK / 4;

    for (int k0 = 0; k0 < K; k0 += BK) {
#pragma unroll
        for (int i = tid; i < A_LD; i += THREADS) {
            int m = i / (BK / 4);
            int kq = i % (BK / 4);
            int gm = m0 + m;
            if (gm >= M) gm = M - 1;
            float4 v = *(const float4*)(A + (size_t)gm * K + k0 + kq * 4);
            As[kq * 4 + 0][m] = v.x;
            As[kq * 4 + 1][m] = v.y;
            As[kq * 4 + 2][m] = v.z;
            As[kq * 4 + 3][m] = v.w;
        }
#pragma unroll
        for (int i = tid; i < W_LD; i += THREADS) {
            int n = i / (BK / 4);
            int kq = i % (BK / 4);
            float4 v = *(const float4*)(W + (size_t)(n0 + n) * K + k0 + kq * 4);
            Ws[kq * 4 + 0][n] = v.x;
            Ws[kq * 4 + 1][n] = v.y;
            Ws[kq * 4 + 2][n] = v.z;
            Ws[kq * 4 + 3][n] = v.w;
        }
        __syncthreads();
#pragma unroll
        for (int k = 0; k < BK; k++) {
            float rm[TM], rn[TN];
#pragma unroll
            for (int i = 0; i < TM; i++) rm[i] = As[k][ty * TM + i];
#pragma unroll
            for (int j = 0; j < TN; j++) rn[j] = Ws[k][tx * TN + j];
#pragma unroll
            for (int i = 0; i < TM; i++)
#pragma unroll
                for (int j = 0; j < TN; j++)
                    acc[i][j] += rm[i] * rn[j];
        }
        __syncthreads();
    }

#pragma unroll
    for (int i = 0; i < TM; i++) {
        int gm = m0 + ty * TM + i;
        float v[TN];
#pragma unroll
        for (int j = 0; j < TN; j++) {
            v[j] = acc[i][j] + bias[n0 + tx * TN + j];
            if (RELU) v[j] = fmaxf(v[j], 0.f);
        }
        if (LSM) {
            // 16 threads (tx 0..15) of this half-warp own the full row
            float mx = v[0];
#pragma unroll
            for (int j = 1; j < TN; j++) mx = fmaxf(mx, v[j]);
#pragma unroll
            for (int o = 1; o < 16; o <<= 1)
                mx = fmaxf(mx, __shfl_xor_sync(0xffffffffu, mx, o));
            float sm = 0.f;
#pragma unroll
            for (int j = 0; j < TN; j++) sm += expf(v[j] - mx);
#pragma unroll
            for (int o = 1; o < 16; o <<= 1)
                sm += __shfl_xor_sync(0xffffffffu, sm, o);
            float l = mx + logf(sm);
#pragma unroll
            for (int j = 0; j < TN; j++) v[j] -= l;
        }
        if (gm < M) {
            if (TN == 4) {
                *(float4*)(C + (size_t)gm * N + n0 + tx * TN) =
                    make_float4(v[0], v[1], v[2], v[3]);
            } else {
#pragma unroll
                for (int j = 0; j < TN; j++)
                    C[(size_t)gm * N + n0 + tx * TN + j] = v[j];
            }
        }
    }
}

// ---------------------------------------------------------------------------
extern "C" void kernel_launch(void* const* d_in, const int* in_sizes, int n_in,
                              void* d_out, int out_size)
{
    const float* x   = (const float*)d_in[0];
    const void*  eix = d_in[1];
    const float* W1  = (const float*)d_in[2];
    const float* b1  = (const float*)d_in[3];
    const float* W2  = (const float*)d_in[4];
    const float* b2  = (const float*)d_in[5];
    float* out = (float*)d_out;

    int N = in_sizes[0] / D1;      // 50000
    int E = in_sizes[1] / 2;       // 800000
    (void)n_in; (void)out_size;

    float *agg1, *h, *agg2, *xn, *hn;
    cudaGetSymbolAddress((void**)&agg1, g_agg1_);
    cudaGetSymbolAddress((void**)&h,    g_h_);
    cudaGetSymbolAddress((void**)&agg2, g_agg2_);
    cudaGetSymbolAddress((void**)&xn,   g_xnorm);
    cudaGetSymbolAddress((void**)&hn,   g_hnorm);

    // dtype detection for edge_index
    k_init_flag<<<1, 1>>>();
    k_detect64<<<(E + 255) / 256, 256>>>(eix, E, N);

    int nodeBlocks = (N * 32 + 255) / 256;

    // ---- Layer 1 (D=128, 2 edges/warp) ----
    k_norms_init<D1><<<nodeBlocks, 256>>>(x, xn, agg1, N);
    {
        long long warps = ((long long)E + 1) / 2;
        int blocks = (int)((warps * 32 + 255) / 256);
        k_edge_pass128<<<blocks, 256>>>(x, xn, eix, agg1, E);
    }
    {
        dim3 grid(256 / 128, (N + 127) / 128);
        k_sgemm<128, 128, 16, 8, 8, 1, 0><<<grid, 256>>>(agg1, W1, b1, h, N, 256, 128);
    }

    // ---- Layer 2 (D=256, 1 edge/warp) ----
    k_norms_init<D2><<<nodeBlocks, 256>>>(h, hn, agg2, N);
    {
        int blocks = (int)(((long long)E * 32 + 255) / 256);
        k_edge_pass256<<<blocks, 256>>>(h, hn, eix, agg2, E);
    }
    {
        dim3 grid(1, (N + 127) / 128);
        k_sgemm<128, 64, 16, 8, 4, 0, 1><<<grid, 256>>>(agg2, W2, b2, out, N, 64, 256);
    }
}

// round 4
// speedup vs baseline: 1.5989x; 1.0231x over previous
#include <cuda_runtime.h>
#include <cuda_bf16.h>
#include <math.h>

#define EPSF 1e-8f
#define NMAX 50000
#define D1 128
#define D2 256
// |dot_bf16 - dot_fp32| <= 2^-8 * ||x|| * ||y|| (Cauchy-Schwarz bound, padded)
#define BF16_MARGIN 0.006f

// Scratch (device globals — no allocation allowed).
__device__ float4 g_agg1_[(size_t)NMAX * D1 / 4];
__device__ float4 g_h_[(size_t)NMAX * D2 / 4];
__device__ float4 g_agg2_[(size_t)NMAX * D2 / 4];
__device__ uint2  g_xb_[(size_t)NMAX * D1 / 4];   // bf16 x, 4 dims per uint2
__device__ uint2  g_hb_[(size_t)NMAX * D2 / 4];   // bf16 h
__device__ float  g_xnorm[NMAX];
__device__ float  g_hnorm[NMAX];
__device__ int    g_is64;

__device__ __forceinline__ uint2 pack_bf16x4(float4 v) {
    __nv_bfloat162 p0 = __floats2bfloat162_rn(v.x, v.y);
    __nv_bfloat162 p1 = __floats2bfloat162_rn(v.z, v.w);
    uint2 r;
    r.x = *(unsigned int*)&p0;
    r.y = *(unsigned int*)&p1;
    return r;
}

__device__ __forceinline__ float dot_bf16x4(uint2 a, uint2 b) {
    float2 a0 = __bfloat1622float2(*(__nv_bfloat162*)&a.x);
    float2 a1 = __bfloat1622float2(*(__nv_bfloat162*)&a.y);
    float2 b0 = __bfloat1622float2(*(__nv_bfloat162*)&b.x);
    float2 b1 = __bfloat1622float2(*(__nv_bfloat162*)&b.y);
    return a0.x * b0.x + a0.y * b0.y + a1.x * b1.x + a1.y * b1.y;
}

// ---------------------------------------------------------------------------
// edge_index dtype detection (jax may serialize int64 as int32)
// ---------------------------------------------------------------------------
__global__ void k_init_flag() { g_is64 = 1; }

__global__ void k_detect64(const void* __restrict__ eidx, int E, int N) {
    int i = blockIdx.x * blockDim.x + threadIdx.x;
    if (i < E) {
        long long v = ((const long long*)eidx)[i];
        if (v < 0 || v >= (long long)N) g_is64 = 0;
    }
}

// ---------------------------------------------------------------------------
// Per-node norms + self-loop init + bf16 conversion.
// agg[i] = (sim_self > 0.5) ? feat[i] : 0
// ---------------------------------------------------------------------------
template<int D>
__global__ void k_norms_init(const float* __restrict__ feat,
                             float* __restrict__ norms,
                             float* __restrict__ agg,
                             uint2* __restrict__ fb, int N)
{
    int node = (blockIdx.x * blockDim.x + threadIdx.x) >> 5;
    int lane = threadIdx.x & 31;
    if (node >= N) return;
    const float4* f = (const float4*)(feat + (size_t)node * D);
    float4* a = (float4*)(agg + (size_t)node * D);
    uint2* fbr = fb + (size_t)node * (D / 4);
    float4 v[D / 128];
    float n2 = 0.f;
#pragma unroll
    for (int i = 0; i < D / 128; i++) {
        v[i] = f[lane + 32 * i];
        n2 += v[i].x * v[i].x + v[i].y * v[i].y + v[i].z * v[i].z + v[i].w * v[i].w;
    }
#pragma unroll
    for (int i = 0; i < D / 128; i++) fbr[lane + 32 * i] = pack_bf16x4(v[i]);
#pragma unroll
    for (int o = 16; o; o >>= 1) n2 += __shfl_xor_sync(0xffffffffu, n2, o);
    float nrm = sqrtf(n2);
    if (lane == 0) norms[node] = nrm;
    float denom = fmaxf(nrm * nrm, EPSF);
    bool pass = n2 > 0.5f * denom;
    float4 z = make_float4(0.f, 0.f, 0.f, 0.f);
#pragma unroll
    for (int i = 0; i < D / 128; i++) a[lane + 32 * i] = pass ? v[i] : z;
}

// ---------------------------------------------------------------------------
// Edge pass: bf16 dot with exact-decision guard band; EPW edges per warp.
// D = dims, V2 = uint2 loads per lane per vector (D/128).
// ---------------------------------------------------------------------------
template<int D, int EPW>
__global__ void k_edge_pass_bf(const float* __restrict__ feat,
                               const uint2* __restrict__ fb,
                               const float* __restrict__ norms,
                               const void* __restrict__ eidx,
                               float* __restrict__ agg, int E)
{
    constexpr int V2 = D / 128;     // uint2 per lane per vector
    long long wid = (long long)((blockIdx.x * (unsigned)blockDim.x + threadIdx.x) >> 5);
    int lane = threadIdx.x & 31;
    long long base = wid * EPW;
    if (base >= E) return;
    const bool is64 = (g_is64 != 0);

    int s[EPW], d[EPW];
#pragma unroll
    for (int k = 0; k < EPW; k++) {
        long long e = base + k;
        if (e >= E) e = E - 1;      // duplicate tail; scatter guarded below
        if (is64) {
            const long long* p = (const long long*)eidx;
            s[k] = (int)p[e];
            d[k] = (int)p[e + E];
        } else {
            const int* p = (const int*)eidx;
            s[k] = p[e];
            d[k] = p[e + E];
        }
    }

    // Prefetch norms before the vector loads
    float nn[EPW];
#pragma unroll
    for (int k = 0; k < EPW; k++) nn[k] = norms[s[k]] * norms[d[k]];

    // bf16 feature loads (half traffic)
    uint2 bs[EPW][V2], bd[EPW][V2];
#pragma unroll
    for (int k = 0; k < EPW; k++) {
        const uint2* ps = fb + (size_t)s[k] * (D / 4);
        const uint2* pd = fb + (size_t)d[k] * (D / 4);
#pragma unroll
        for (int i = 0; i < V2; i++) {
            bs[k][i] = ps[lane + 32 * i];
            bd[k][i] = pd[lane + 32 * i];
        }
    }

    float t[EPW];
#pragma unroll
    for (int k = 0; k < EPW; k++) {
        float acc = 0.f;
#pragma unroll
        for (int i = 0; i < V2; i++) acc += dot_bf16x4(bs[k][i], bd[k][i]);
        t[k] = acc;
    }
    // interleaved butterflies
#pragma unroll
    for (int o = 16; o; o >>= 1) {
#pragma unroll
        for (int k = 0; k < EPW; k++)
            t[k] += __shfl_xor_sync(0xffffffffu, t[k], o);
    }

#pragma unroll
    for (int k = 0; k < EPW; k++) {
        if (EPW > 1 && base + k >= E) break;
        float thr = 0.5f * fmaxf(nn[k], EPSF);
        float margin = BF16_MARGIN * nn[k];
        float dot = t[k];
        bool pass;
        if (fabsf(dot - thr) > margin) {
            pass = (dot > thr);                    // certain from bf16
        } else {
            // rescue: exact fp32 dot (warp-uniform, rare)
            const float4* fs = (const float4*)(feat + (size_t)s[k] * D);
            const float4* fd = (const float4*)(feat + (size_t)d[k] * D);
            float ex = 0.f;
#pragma unroll
            for (int i = 0; i < D / 128; i++) {
                float4 a = fs[lane + 32 * i];
                float4 b = fd[lane + 32 * i];
                ex += a.x * b.x + a.y * b.y + a.z * b.z + a.w * b.w;
            }
#pragma unroll
            for (int o = 16; o; o >>= 1) ex += __shfl_xor_sync(0xffffffffu, ex, o);
            pass = (ex > thr);
        }
        if (pass) {
            // scatter exact fp32 source features (rare)
            const float4* fs = (const float4*)(feat + (size_t)s[k] * D);
            float* out = agg + (size_t)d[k] * D + lane * 4;
#pragma unroll
            for (int i = 0; i < D / 128; i++) {
                float4 a = fs[lane + 32 * i];
                asm volatile("red.global.add.v4.f32 [%0], {%1,%2,%3,%4};" ::
                             "l"(out + i * 128),
                             "f"(a.x), "f"(a.y), "f"(a.z), "f"(a.w)
                             : "memory");
            }
        }
    }
}

// ---------------------------------------------------------------------------
// SGEMM: C[M,N] = A[M,K] @ W[N,K]^T + bias. RELU or fused log_softmax
// (LSM requires BN == N == 16*TN so each half-warp owns full rows).
// ---------------------------------------------------------------------------
template<int BM, int BN, int BK, int TM, int TN, int RELU, int LSM>
__global__ __launch_bounds__((BM / TM) * (BN / TN))
void k_sgemm(const float* __restrict__ A, const float* __restrict__ W,
             const float* __restrict__ bias, float* __restrict__ C,
             int M, int N, int K)
{
    constexpr int THREADS = (BM / TM) * (BN / TN);
    __shared__ float As[BK][BM];
    __shared__ float Ws[BK][BN];
    int tid = threadIdx.x;
    int tx = tid % (BN / TN);
    int ty = tid / (BN / TN);
    int m0 = blockIdx.y * BM;
    int n0 = blockIdx.x * BN;

    float acc[TM][TN] = {};
    constexpr int A_LD = BM * BK / 4;
    constexpr int W_LD = BN * BK / 4;

    for (int k0 = 0; k0 < K; k0 += BK) {
#pragma unroll
        for (int i = tid; i < A_LD; i += THREADS) {
            int m = i / (BK / 4);
            int kq = i % (BK / 4);
            int gm = m0 + m;
            if (gm >= M) gm = M - 1;
            float4 v = *(const float4*)(A + (size_t)gm * K + k0 + kq * 4);
            As[kq * 4 + 0][m] = v.x;
            As[kq * 4 + 1][m] = v.y;
            As[kq * 4 + 2][m] = v.z;
            As[kq * 4 + 3][m] = v.w;
        }
#pragma unroll
        for (int i = tid; i < W_LD; i += THREADS) {
            int n = i / (BK / 4);
            int kq = i % (BK / 4);
            float4 v = *(const float4*)(W + (size_t)(n0 + n) * K + k0 + kq * 4);
            Ws[kq * 4 + 0][n] = v.x;
            Ws[kq * 4 + 1][n] = v.y;
            Ws[kq * 4 + 2][n] = v.z;
            Ws[kq * 4 + 3][n] = v.w;
        }
        __syncthreads();
#pragma unroll
        for (int k = 0; k < BK; k++) {
            float rm[TM], rn[TN];
#pragma unroll
            for (int i = 0; i < TM; i++) rm[i] = As[k][ty * TM + i];
#pragma unroll
            for (int j = 0; j < TN; j++) rn[j] = Ws[k][tx * TN + j];
#pragma unroll
            for (int i = 0; i < TM; i++)
#pragma unroll
                for (int j = 0; j < TN; j++)
                    acc[i][j] += rm[i] * rn[j];
        }
        __syncthreads();
    }

#pragma unroll
    for (int i = 0; i < TM; i++) {
        int gm = m0 + ty * TM + i;
        float v[TN];
#pragma unroll
        for (int j = 0; j < TN; j++) {
            v[j] = acc[i][j] + bias[n0 + tx * TN + j];
            if (RELU) v[j] = fmaxf(v[j], 0.f);
        }
        if (LSM) {
            float mx = v[0];
#pragma unroll
            for (int j = 1; j < TN; j++) mx = fmaxf(mx, v[j]);
#pragma unroll
            for (int o = 1; o < 16; o <<= 1)
                mx = fmaxf(mx, __shfl_xor_sync(0xffffffffu, mx, o));
            float sm = 0.f;
#pragma unroll
            for (int j = 0; j < TN; j++) sm += expf(v[j] - mx);
#pragma unroll
            for (int o = 1; o < 16; o <<= 1)
                sm += __shfl_xor_sync(0xffffffffu, sm, o);
            float l = mx + logf(sm);
#pragma unroll
            for (int j = 0; j < TN; j++) v[j] -= l;
        }
        if (gm < M) {
            if (TN == 4) {
                *(float4*)(C + (size_t)gm * N + n0 + tx * TN) =
                    make_float4(v[0], v[1], v[2], v[3]);
            } else {
#pragma unroll
                for (int j = 0; j < TN; j++)
                    C[(size_t)gm * N + n0 + tx * TN + j] = v[j];
            }
        }
    }
}

// ---------------------------------------------------------------------------
extern "C" void kernel_launch(void* const* d_in, const int* in_sizes, int n_in,
                              void* d_out, int out_size)
{
    const float* x   = (const float*)d_in[0];
    const void*  eix = d_in[1];
    const float* W1  = (const float*)d_in[2];
    const float* b1  = (const float*)d_in[3];
    const float* W2  = (const float*)d_in[4];
    const float* b2  = (const float*)d_in[5];
    float* out = (float*)d_out;

    int N = in_sizes[0] / D1;      // 50000
    int E = in_sizes[1] / 2;       // 800000
    (void)n_in; (void)out_size;

    float *agg1, *h, *agg2, *xn, *hn;
    uint2 *xb, *hb;
    cudaGetSymbolAddress((void**)&agg1, g_agg1_);
    cudaGetSymbolAddress((void**)&h,    g_h_);
    cudaGetSymbolAddress((void**)&agg2, g_agg2_);
    cudaGetSymbolAddress((void**)&xb,   g_xb_);
    cudaGetSymbolAddress((void**)&hb,   g_hb_);
    cudaGetSymbolAddress((void**)&xn,   g_xnorm);
    cudaGetSymbolAddress((void**)&hn,   g_hnorm);

    k_init_flag<<<1, 1>>>();
    k_detect64<<<(E + 255) / 256, 256>>>(eix, E, N);

    int nodeBlocks = (N * 32 + 255) / 256;

    // ---- Layer 1 (D=128, 2 edges/warp, bf16 dots) ----
    k_norms_init<D1><<<nodeBlocks, 256>>>(x, xn, agg1, xb, N);
    {
        long long warps = ((long long)E + 1) / 2;
        int blocks = (int)((warps * 32 + 255) / 256);
        k_edge_pass_bf<D1, 2><<<blocks, 256>>>(x, xb, xn, eix, agg1, E);
    }
    {
        dim3 grid(256 / 128, (N + 127) / 128);
        k_sgemm<128, 128, 16, 8, 8, 1, 0><<<grid, 256>>>(agg1, W1, b1, h, N, 256, 128);
    }

    // ---- Layer 2 (D=256, 2 edges/warp, bf16 dots) ----
    k_norms_init<D2><<<nodeBlocks, 256>>>(h, hn, agg2, hb, N);
    {
        long long warps = ((long long)E + 1) / 2;
        int blocks = (int)((warps * 32 + 255) / 256);
        k_edge_pass_bf<D2, 2><<<blocks, 256>>>(h, hb, hn, eix, agg2, E);
    }
    {
        dim3 grid(1, (N + 127) / 128);
        k_sgemm<128, 64, 16, 8, 4, 0, 1><<<grid, 256>>>(agg2, W2, b2, out, N, 64, 256);
    }
}

// round 5
// speedup vs baseline: 1.7603x; 1.1009x over previous
#include <cuda_runtime.h>
#include <cuda_bf16.h>
#include <math.h>

#define EPSF 1e-8f
#define NMAX 50000
#define D1 128
#define D2 256
// HFMA2-chain dot abs error <= 2^-6 * ||x||*||y|| (4 fused roundings/lane chain)
#define BF16_MARGIN 0.02f

// Scratch (device globals — no allocation allowed).
__device__ float4 g_agg1_[(size_t)NMAX * D1 / 4];
__device__ float4 g_h_[(size_t)NMAX * D2 / 4];
__device__ float4 g_agg2_[(size_t)NMAX * D2 / 4];
__device__ uint4  g_xb_[(size_t)NMAX * D1 / 8];   // bf16 x (16B aligned)
__device__ uint4  g_hb_[(size_t)NMAX * D2 / 8];   // bf16 h
__device__ float  g_xnorm[NMAX];
__device__ float  g_hnorm[NMAX];
__device__ int    g_is64;

__device__ __forceinline__ uint2 pack_bf16x4(float4 v) {
    __nv_bfloat162 p0 = __floats2bfloat162_rn(v.x, v.y);
    __nv_bfloat162 p1 = __floats2bfloat162_rn(v.z, v.w);
    uint2 r;
    r.x = *(unsigned int*)&p0;
    r.y = *(unsigned int*)&p1;
    return r;
}

// bf16x2 HFMA2 chain over one uint4 (8 bf16 pairs)
__device__ __forceinline__ __nv_bfloat162 hfma_u4(uint4 a, uint4 b, __nv_bfloat162 acc) {
    const __nv_bfloat162* pa = (const __nv_bfloat162*)&a;
    const __nv_bfloat162* pb = (const __nv_bfloat162*)&b;
#pragma unroll
    for (int i = 0; i < 4; i++) acc = __hfma2(pa[i], pb[i], acc);
    return acc;
}

// ---------------------------------------------------------------------------
// edge_index dtype detection (jax may serialize int64 as int32)
// ---------------------------------------------------------------------------
__global__ void k_init_flag() { g_is64 = 1; }

__global__ void k_detect64(const void* __restrict__ eidx, int E, int N) {
    int i = blockIdx.x * blockDim.x + threadIdx.x;
    if (i < E) {
        long long v = ((const long long*)eidx)[i];
        if (v < 0 || v >= (long long)N) g_is64 = 0;
    }
}

// ---------------------------------------------------------------------------
// Per-node norms + self-loop init + bf16 conversion.
// ---------------------------------------------------------------------------
template<int D>
__global__ void k_norms_init(const float* __restrict__ feat,
                             float* __restrict__ norms,
                             float* __restrict__ agg,
                             uint2* __restrict__ fb, int N)
{
    int node = (blockIdx.x * blockDim.x + threadIdx.x) >> 5;
    int lane = threadIdx.x & 31;
    if (node >= N) return;
    const float4* f = (const float4*)(feat + (size_t)node * D);
    float4* a = (float4*)(agg + (size_t)node * D);
    uint2* fbr = fb + (size_t)node * (D / 4);
    float4 v[D / 128];
    float n2 = 0.f;
#pragma unroll
    for (int i = 0; i < D / 128; i++) {
        v[i] = f[lane + 32 * i];
        n2 += v[i].x * v[i].x + v[i].y * v[i].y + v[i].z * v[i].z + v[i].w * v[i].w;
    }
#pragma unroll
    for (int i = 0; i < D / 128; i++) fbr[lane + 32 * i] = pack_bf16x4(v[i]);
#pragma unroll
    for (int o = 16; o; o >>= 1) n2 += __shfl_xor_sync(0xffffffffu, n2, o);
    float nrm = sqrtf(n2);
    if (lane == 0) norms[node] = nrm;
    float denom = fmaxf(nrm * nrm, EPSF);
    bool pass = n2 > 0.5f * denom;
    float4 z = make_float4(0.f, 0.f, 0.f, 0.f);
#pragma unroll
    for (int i = 0; i < D / 128; i++) a[lane + 32 * i] = pass ? v[i] : z;
}

// ---------------------------------------------------------------------------
// Edge pass, half-warp per edge (16 lanes/edge, 2 edges/warp).
// U4 = uint4 bf16 loads per lane per endpoint (1 for D=128, 2 for D=256).
// ---------------------------------------------------------------------------
template<int D, int U4>
__global__ void k_edge_half(const float* __restrict__ feat,
                            const uint4* __restrict__ fb,
                            const float* __restrict__ norms,
                            const void* __restrict__ eidx,
                            float* __restrict__ agg, int E)
{
    constexpr int NSTRIDE = D / 8;  // uint4 per node row
    long long wid = (long long)((blockIdx.x * (unsigned)blockDim.x + threadIdx.x) >> 5);
    if (wid * 2 >= E) return;
    int lane = threadIdx.x & 31;
    int sl = lane & 15;
    long long e = wid * 2 + (lane >> 4);
    bool valid = (e < E);
    long long ec = valid ? e : (long long)E - 1;

    int s, d;
    if (g_is64) {
        const long long* p = (const long long*)eidx;
        s = (int)p[ec];
        d = (int)p[ec + E];
    } else {
        const int* p = (const int*)eidx;
        s = p[ec];
        d = p[ec + E];
    }
    float nn = norms[s] * norms[d];

    const uint4* ps = fb + (size_t)s * NSTRIDE;
    const uint4* pd = fb + (size_t)d * NSTRIDE;

    float t;
    {
        uint4 a0 = ps[sl];
        uint4 b0 = pd[sl];
        __nv_bfloat162 z2 = __float2bfloat162_rn(0.f);
        __nv_bfloat162 acc0 = hfma_u4(a0, b0, z2);
        float2 f0 = __bfloat1622float2(acc0);
        t = f0.x + f0.y;
        if (U4 == 2) {
            uint4 a1 = ps[sl + 16];
            uint4 b1 = pd[sl + 16];
            __nv_bfloat162 acc1 = hfma_u4(a1, b1, z2);
            float2 f1 = __bfloat1622float2(acc1);
            t += f1.x + f1.y;
        }
    }
    // reduce within each 16-lane half (all 32 lanes converged)
#pragma unroll
    for (int o = 1; o < 16; o <<= 1) t += __shfl_xor_sync(0xffffffffu, t, o);

    float thr = 0.5f * fmaxf(nn, EPSF);
    float margin = BF16_MARGIN * nn;
    bool pass;
    if (fabsf(t - thr) > margin) {
        pass = (t > thr);
    } else {
        // rescue: exact fp32 dot within this half-warp (rare, may diverge per half)
        unsigned hm = 0xffffu << (lane & 16);
        const float4* fs = (const float4*)(feat + (size_t)s * D);
        const float4* fd = (const float4*)(feat + (size_t)d * D);
        float ex = 0.f;
#pragma unroll
        for (int i = 0; i < D / 64; i++) {
            float4 a = fs[sl + 16 * i];
            float4 b = fd[sl + 16 * i];
            ex += a.x * b.x + a.y * b.y + a.z * b.z + a.w * b.w;
        }
#pragma unroll
        for (int o = 1; o < 16; o <<= 1) ex += __shfl_xor_sync(hm, ex, o);
        pass = (ex > thr);
    }

    if (valid && pass) {
        // scatter exact fp32 source features (rare)
        const float4* fs = (const float4*)(feat + (size_t)s * D);
        float* out = agg + (size_t)d * D;
#pragma unroll
        for (int i = 0; i < D / 64; i++) {
            float4 a = fs[sl + 16 * i];
            asm volatile("red.global.add.v4.f32 [%0], {%1,%2,%3,%4};" ::
                         "l"(out + (sl + 16 * i) * 4),
                         "f"(a.x), "f"(a.y), "f"(a.z), "f"(a.w)
                         : "memory");
        }
    }
}

// ---------------------------------------------------------------------------
// SGEMM: C[M,N] = A[M,K] @ W[N,K]^T + bias. RELU or fused log_softmax
// (LSM requires BN == N == 16*TN so each half-warp owns full rows).
// ---------------------------------------------------------------------------
template<int BM, int BN, int BK, int TM, int TN, int RELU, int LSM>
__global__ __launch_bounds__((BM / TM) * (BN / TN))
void k_sgemm(const float* __restrict__ A, const float* __restrict__ W,
             const float* __restrict__ bias, float* __restrict__ C,
             int M, int N, int K)
{
    constexpr int THREADS = (BM / TM) * (BN / TN);
    __shared__ float As[BK][BM];
    __shared__ float Ws[BK][BN];
    int tid = threadIdx.x;
    int tx = tid % (BN / TN);
    int ty = tid / (BN / TN);
    int m0 = blockIdx.y * BM;
    int n0 = blockIdx.x * BN;

    float acc[TM][TN] = {};
    constexpr int A_LD = BM * BK / 4;
    constexpr int W_LD = BN * BK / 4;

    for (int k0 = 0; k0 < K; k0 += BK) {
#pragma unroll
        for (int i = tid; i < A_LD; i += THREADS) {
            int m = i / (BK / 4);
            int kq = i % (BK / 4);
            int gm = m0 + m;
            if (gm >= M) gm = M - 1;
            float4 v = *(const float4*)(A + (size_t)gm * K + k0 + kq * 4);
            As[kq * 4 + 0][m] = v.x;
            As[kq * 4 + 1][m] = v.y;
            As[kq * 4 + 2][m] = v.z;
            As[kq * 4 + 3][m] = v.w;
        }
#pragma unroll
        for (int i = tid; i < W_LD; i += THREADS) {
            int n = i / (BK / 4);
            int kq = i % (BK / 4);
            float4 v = *(const float4*)(W + (size_t)(n0 + n) * K + k0 + kq * 4);
            Ws[kq * 4 + 0][n] = v.x;
            Ws[kq * 4 + 1][n] = v.y;
            Ws[kq * 4 + 2][n] = v.z;
            Ws[kq * 4 + 3][n] = v.w;
        }
        __syncthreads();
#pragma unroll
        for (int k = 0; k < BK; k++) {
            float rm[TM], rn[TN];
#pragma unroll
            for (int i = 0; i < TM; i++) rm[i] = As[k][ty * TM + i];
#pragma unroll
            for (int j = 0; j < TN; j++) rn[j] = Ws[k][tx * TN + j];
#pragma unroll
            for (int i = 0; i < TM; i++)
#pragma unroll
                for (int j = 0; j < TN; j++)
                    acc[i][j] += rm[i] * rn[j];
        }
        __syncthreads();
    }

#pragma unroll
    for (int i = 0; i < TM; i++) {
        int gm = m0 + ty * TM + i;
        float v[TN];
#pragma unroll
        for (int j = 0; j < TN; j++) {
            v[j] = acc[i][j] + bias[n0 + tx * TN + j];
            if (RELU) v[j] = fmaxf(v[j], 0.f);
        }
        if (LSM) {
            float mx = v[0];
#pragma unroll
            for (int j = 1; j < TN; j++) mx = fmaxf(mx, v[j]);
#pragma unroll
            for (int o = 1; o < 16; o <<= 1)
                mx = fmaxf(mx, __shfl_xor_sync(0xffffffffu, mx, o));
            float sm = 0.f;
#pragma unroll
            for (int j = 0; j < TN; j++) sm += expf(v[j] - mx);
#pragma unroll
            for (int o = 1; o < 16; o <<= 1)
                sm += __shfl_xor_sync(0xffffffffu, sm, o);
            float l = mx + logf(sm);
#pragma unroll
            for (int j = 0; j < TN; j++) v[j] -= l;
        }
        if (gm < M) {
            if (TN == 4) {
                *(float4*)(C + (size_t)gm * N + n0 + tx * TN) =
                    make_float4(v[0], v[1], v[2], v[3]);
            } else {
#pragma unroll
                for (int j = 0; j < TN; j++)
                    C[(size_t)gm * N + n0 + tx * TN + j] = v[j];
            }
        }
    }
}

// ---------------------------------------------------------------------------
extern "C" void kernel_launch(void* const* d_in, const int* in_sizes, int n_in,
                              void* d_out, int out_size)
{
    const float* x   = (const float*)d_in[0];
    const void*  eix = d_in[1];
    const float* W1  = (const float*)d_in[2];
    const float* b1  = (const float*)d_in[3];
    const float* W2  = (const float*)d_in[4];
    const float* b2  = (const float*)d_in[5];
    float* out = (float*)d_out;

    int N = in_sizes[0] / D1;      // 50000
    int E = in_sizes[1] / 2;       // 800000
    (void)n_in; (void)out_size;

    float *agg1, *h, *agg2, *xn, *hn;
    uint4 *xb, *hb;
    cudaGetSymbolAddress((void**)&agg1, g_agg1_);
    cudaGetSymbolAddress((void**)&h,    g_h_);
    cudaGetSymbolAddress((void**)&agg2, g_agg2_);
    cudaGetSymbolAddress((void**)&xb,   g_xb_);
    cudaGetSymbolAddress((void**)&hb,   g_hb_);
    cudaGetSymbolAddress((void**)&xn,   g_xnorm);
    cudaGetSymbolAddress((void**)&hn,   g_hnorm);

    k_init_flag<<<1, 1>>>();
    k_detect64<<<(E + 255) / 256, 256>>>(eix, E, N);

    int nodeBlocks = (N * 32 + 255) / 256;
    long long warps = ((long long)E + 1) / 2;
    int edgeBlocks = (int)((warps * 32 + 255) / 256);

    // ---- Layer 1 (D=128) ----
    k_norms_init<D1><<<nodeBlocks, 256>>>(x, xn, agg1, (uint2*)xb, N);
    k_edge_half<D1, 1><<<edgeBlocks, 256>>>(x, xb, xn, eix, agg1, E);
    {
        dim3 grid(256 / 128, (N + 127) / 128);
        k_sgemm<128, 128, 16, 8, 8, 1, 0><<<grid, 256>>>(agg1, W1, b1, h, N, 256, 128);
    }

    // ---- Layer 2 (D=256) ----
    k_norms_init<D2><<<nodeBlocks, 256>>>(h, hn, agg2, (uint2*)hb, N);
    k_edge_half<D2, 2><<<edgeBlocks, 256>>>(h, hb, hn, eix, agg2, E);
    {
        dim3 grid(1, (N + 127) / 128);
        k_sgemm<128, 64, 16, 8, 4, 0, 1><<<grid, 256>>>(agg2, W2, b2, out, N, 64, 256);
    }
}